// round 15
// baseline (speedup 1.0000x reference)
#include <cuda_runtime.h>
#include <cuda_bf16.h>
#include <math.h>
#include <stdint.h>

// Problem constants
#define BB   512
#define LL   128
#define DD   300
#define RR   256
#define SAA  256

typedef unsigned long long ull;

// ---------------------------------------------------------------------------
// Scratch (device globals — no allocation allowed)
// ---------------------------------------------------------------------------
__device__ float g_Lseq[(size_t)BB * LL * RR];   // 67 MB
__device__ float g_G1  [(size_t)BB * LL * SAA]; // 67 MB
__device__ float g_G2  [(size_t)BB * LL * SAA]; // 67 MB

// Packed weights: P[k4*256 + s] = {W[4k4+0][s], .., W[4k4+3][s]}
__device__ float4 g_Pw1 [64 * 256];   // Wss1
__device__ float4 g_Pw2 [64 * 256];   // Wss2
__device__ float4 g_PwrA[64 * 256];   // Wrs1
__device__ float4 g_PwrB[64 * 256];   // Wrs2
__device__ float4 g_Pt1 [64 * 256];   // trans_r1
__device__ float4 g_Ptw [64 * 256];   // trans_wildcard (streamed from L2 in scan)
__device__ float4 g_Pt2 [64 * 256];   // trans_r2^T
__device__ float4 g_Perg[75 * 256];   // embed_r_gen

// ---------------------------------------------------------------------------
// f32x2 packed-fp32 helpers
// ---------------------------------------------------------------------------
__device__ __forceinline__ void ffma2(ull &acc, ull a, ull b) {
    asm("fma.rn.f32x2 %0, %1, %2, %0;" : "+l"(acc) : "l"(a), "l"(b));
}
__device__ __forceinline__ float sum2(ull v) {
    float a, b; asm("mov.b64 {%0, %1}, %2;" : "=f"(a), "=f"(b) : "l"(v));
    return a + b;
}
__device__ __forceinline__ float sigmoid_f(float x) {
    return 1.0f / (1.0f + __expf(-x));
}
__device__ __forceinline__ float tanh_f(float x) {
    return 1.0f - 2.0f / (__expf(2.0f * x) + 1.0f);
}

// Cluster / mbarrier helpers
__device__ __forceinline__ uint32_t smem_u32(const void* p) {
    uint32_t a;
    asm("{ .reg .u64 t; cvta.to.shared.u64 t, %1; cvt.u32.u64 %0, t; }" : "=r"(a) : "l"(p));
    return a;
}
__device__ __forceinline__ uint32_t mapa_u32(uint32_t saddr, int rank) {
    uint32_t r;
    asm("mapa.shared::cluster.u32 %0, %1, %2;" : "=r"(r) : "r"(saddr), "r"(rank));
    return r;
}
__device__ __forceinline__ void cluster_sync() {
    asm volatile("barrier.cluster.arrive.aligned;" ::: "memory");
    asm volatile("barrier.cluster.wait.aligned;" ::: "memory");
}
__device__ __forceinline__ uint32_t ctarank() {
    uint32_t r; asm("mov.u32 %0, %%cluster_ctarank;" : "=r"(r)); return r;
}
__device__ __forceinline__ void mbar_init(uint32_t bar, uint32_t cnt) {
    asm volatile("mbarrier.init.shared.b64 [%0], %1;" :: "r"(bar), "r"(cnt) : "memory");
}
__device__ __forceinline__ void mbar_arrive_expect_tx(uint32_t bar, uint32_t bytes) {
    asm volatile("mbarrier.arrive.expect_tx.shared.b64 _, [%0], %1;"
                 :: "r"(bar), "r"(bytes) : "memory");
}
__device__ __forceinline__ void mbar_wait_parity(uint32_t bar, uint32_t parity) {
    asm volatile(
        "{\n\t"
        ".reg .pred P1;\n\t"
        "WAIT_%=:\n\t"
        "mbarrier.try_wait.parity.acquire.cta.shared::cta.b64 P1, [%0], %1, 0x989680;\n\t"
        "@P1 bra.uni DONE_%=;\n\t"
        "bra.uni WAIT_%=;\n\t"
        "DONE_%=:\n\t"
        "}"
        :: "r"(bar), "r"(parity) : "memory");
}
__device__ __forceinline__ void fence_proxy_async_cta() {
    asm volatile("fence.proxy.async.shared::cta;" ::: "memory");
}
// SMEM (local) -> peer CTA SMEM bulk copy with complete_tx on peer's mbarrier.
__device__ __forceinline__ void bulk_copy_peer(uint32_t dst_cluster, uint32_t src_cta,
                                               uint32_t bytes, uint32_t peer_mbar) {
    asm volatile(
        "cp.async.bulk.shared::cluster.shared::cta.mbarrier::complete_tx::bytes "
        "[%0], [%1], %2, [%3];"
        :: "r"(dst_cluster), "r"(src_cta), "r"(bytes), "r"(peer_mbar) : "memory");
}
// Drain all outstanding outbound bulk copies issued by this thread.
__device__ __forceinline__ void bulk_drain() {
    asm volatile("cp.async.bulk.commit_group;" ::: "memory");
    asm volatile("cp.async.bulk.wait_group.read 0;" ::: "memory");
}
// Named barrier over 256 threads (ids 1 and 2 for the two halves).
__device__ __forceinline__ void half_bar(int id) {
    asm volatile("bar.sync %0, 256;" :: "r"(id) : "memory");
}

// ---------------------------------------------------------------------------
// Kernel 0: pack all weight matrices into float4-over-k layout.
// ---------------------------------------------------------------------------
__global__ __launch_bounds__(256) void pack_weights(
    const float* __restrict__ Wss1, const float* __restrict__ Wss2,
    const float* __restrict__ Wrs1, const float* __restrict__ Wrs2,
    const float* __restrict__ tr1,  const float* __restrict__ tw,
    const float* __restrict__ tr2,  const float* __restrict__ erg)
{
    const int bx = blockIdx.x;
    const int m  = bx / 75;
    const int k4 = bx % 75;
    const int s  = threadIdx.x;

    if (m == 0) {
        g_Perg[k4 * 256 + s] = make_float4(
            erg[(4 * k4 + 0) * RR + s], erg[(4 * k4 + 1) * RR + s],
            erg[(4 * k4 + 2) * RR + s], erg[(4 * k4 + 3) * RR + s]);
        return;
    }
    if (k4 >= 64) return;

    const int k = 4 * k4;
    switch (m) {
        case 1: g_Pw1 [k4 * 256 + s] = make_float4(Wss1[(k+0)*SAA+s], Wss1[(k+1)*SAA+s], Wss1[(k+2)*SAA+s], Wss1[(k+3)*SAA+s]); break;
        case 2: g_Pw2 [k4 * 256 + s] = make_float4(Wss2[(k+0)*SAA+s], Wss2[(k+1)*SAA+s], Wss2[(k+2)*SAA+s], Wss2[(k+3)*SAA+s]); break;
        case 3: g_PwrA[k4 * 256 + s] = make_float4(Wrs1[(k+0)*SAA+s], Wrs1[(k+1)*SAA+s], Wrs1[(k+2)*SAA+s], Wrs1[(k+3)*SAA+s]); break;
        case 4: g_PwrB[k4 * 256 + s] = make_float4(Wrs2[(k+0)*SAA+s], Wrs2[(k+1)*SAA+s], Wrs2[(k+2)*SAA+s], Wrs2[(k+3)*SAA+s]); break;
        case 5: g_Pt1 [k4 * 256 + s] = make_float4(tr1 [(k+0)*RR +s], tr1 [(k+1)*RR +s], tr1 [(k+2)*RR +s], tr1 [(k+3)*RR +s]); break;
        case 6: g_Ptw [k4 * 256 + s] = make_float4(tw  [(k+0)*SAA+s], tw  [(k+1)*SAA+s], tw  [(k+2)*SAA+s], tw  [(k+3)*SAA+s]); break;
        case 7: g_Pt2 [k4 * 256 + s] = *reinterpret_cast<const float4*>(&tr2[s * RR + k]); break;
    }
}

// ---------------------------------------------------------------------------
// Kernel 1: token-parallel precompute (unchanged).
// ---------------------------------------------------------------------------
#define TOK 16

__global__ __launch_bounds__(256) void precompute_kernel(
    const int*   __restrict__ ids,
    const float* __restrict__ embedding,
    const float* __restrict__ embed_r,
    const float* __restrict__ bs1,
    const float* __restrict__ bs2,
    const float* __restrict__ beta)
{
    __shared__ int   s_id[TOK];
    __shared__ float s_emb[TOK * 304];
    __shared__ float s_Lt[TOK * RR];

    const int tid  = threadIdx.x;
    const int tok0 = blockIdx.x * TOK;

    if (tid < TOK) s_id[tid] = ids[tok0 + tid];
    __syncthreads();

    for (int i = tid; i < TOK * DD; i += 256) {
        int t = i / DD;
        int d = i - t * DD;
        s_emb[t * 304 + d] = embedding[(long)s_id[t] * DD + d];
    }
    __syncthreads();

    const int r = tid;
    const float beta_r = beta[r];

    ull acc[TOK];
#pragma unroll
    for (int t = 0; t < TOK; t++) acc[t] = 0ULL;

#pragma unroll 5
    for (int d4 = 0; d4 < 75; d4++) {
        ulonglong2 w = *reinterpret_cast<const ulonglong2*>(&g_Perg[d4 * 256 + r]);
#pragma unroll
        for (int t = 0; t < TOK; t++) {
            ulonglong2 e = *reinterpret_cast<const ulonglong2*>(&s_emb[t * 304 + 4 * d4]);
            ffma2(acc[t], e.x, w.x);
            ffma2(acc[t], e.y, w.y);
        }
    }

#pragma unroll
    for (int t = 0; t < TOK; t++) {
        float lg = tanh_f(sum2(acc[t]));
        float er = embed_r[(long)s_id[t] * RR + r];
        float v  = er * beta_r + lg * (1.0f - beta_r);
        s_Lt[t * RR + r] = v;
        g_Lseq[(long)(tok0 + t) * RR + r] = v;
    }
    __syncthreads();

    ull a1[TOK], a2[TOK];
#pragma unroll
    for (int t = 0; t < TOK; t++) { a1[t] = 0ULL; a2[t] = 0ULL; }

#pragma unroll 4
    for (int k4 = 0; k4 < 64; k4++) {
        ulonglong2 w1 = *reinterpret_cast<const ulonglong2*>(&g_PwrA[k4 * 256 + r]);
        ulonglong2 w2 = *reinterpret_cast<const ulonglong2*>(&g_PwrB[k4 * 256 + r]);
#pragma unroll
        for (int t = 0; t < TOK; t++) {
            ulonglong2 lv = *reinterpret_cast<const ulonglong2*>(&s_Lt[t * RR + 4 * k4]);
            ffma2(a1[t], lv.x, w1.x);
            ffma2(a1[t], lv.y, w1.y);
            ffma2(a2[t], lv.x, w2.x);
            ffma2(a2[t], lv.y, w2.y);
        }
    }

    const float b1v = bs1[r];
    const float b2v = bs2[r];
#pragma unroll
    for (int t = 0; t < TOK; t++) {
        g_G1[(long)(tok0 + t) * SAA + r] = sum2(a1[t]) + b1v;
        g_G2[(long)(tok0 + t) * SAA + r] = sum2(a2[t]) + b2v;
    }
}

// ---------------------------------------------------------------------------
// Kernel 2: clustered scan — TWO INDEPENDENT HALF-CTAS per CTA.
// (R13 design with the init-loop OOB fixed: bound 8192, hf in {0,1}; plus
// outbound bulk-copy drain + cluster_sync at exit.)
//
// 16 clusters x 8 CTAs x 512 threads. Warps 0-7 (half 0) own batch rows
// [0,16); warps 8-15 (half 1) own rows [16,32). Halves share nothing in the
// loop: own buffers, own mbarriers, own 2KB bulk-copy exchanges, named
// barriers (bar.sync 1 / bar.sync 2).
//
// Per-half buffer regions (4096 floats): A (h), Bf (hbar), C (LRv/partials),
// block-major [8 blocks][16 rows][32 cols] (512 floats/block).
// Matmul role (8 warps/half): rg=wh>>2 -> rows [8rg,8rg+8), ks=wh&3 -> k in
// [64ks,64ks+64). Partials in dead regions (liveness gated by the mbarrier
// data chain as in R11/R12). Finalize: warp wh owns rows [2wh,2wh+2).
// ---------------------------------------------------------------------------
#define OFF_A   0
#define OFF_B   8192
#define OFF_C   16384
#define OFF_W1  24576
#define OFF_W2  (24576 + 8192)
#define OFF_T1  (24576 + 16384)
#define OFF_T2  (24576 + 24576)
#define OFF_MBAR 57344                        // 6 mbarriers (8B each)
#define SMEM_FLOATS (57344 + 16)              // 229440 bytes

#define XTX (7u * 2048u)                       // expected bytes per half exchange

__global__ void __cluster_dims__(8, 1, 1) __launch_bounds__(512, 1)
scan_kernel(const float* __restrict__ h1, float* __restrict__ out,
            int l_start, int l_end)
{
    extern __shared__ float sm[];
    const int tid  = threadIdx.x;
    const int half = tid >> 8;                 // 0 or 1
    const int ht   = tid & 255;                // thread within half
    const int wh   = ht >> 5;                  // warp within half (0..7)
    const int col  = tid & 31;
    const int rg   = wh >> 2;                  // matmul row group (8 rows)
    const int ks   = wh & 3;                   // matmul k-slice (64 k)
    const int rbase = rg * 8;
    const int kb4  = ks * 16;
    const int barid = half + 1;                // named barrier id
    const uint32_t rank = ctarank();
    const int sg   = (int)rank * 32 + col;     // global state column
    const int b0   = (blockIdx.x >> 3) * 32 + half * 16;  // this half's first row

    float* Ah = sm + OFF_A + half * 4096;
    float* Bh = sm + OFF_B + half * 4096;
    float* Ch = sm + OFF_C + half * 4096;
    float4* w1 = reinterpret_cast<float4*>(sm + OFF_W1);
    float4* w2 = reinterpret_cast<float4*>(sm + OFF_W2);
    float4* t1 = reinterpret_cast<float4*>(sm + OFF_T1);
    float4* t2 = reinterpret_cast<float4*>(sm + OFF_T2);

    const uint32_t base_local = smem_u32(sm);
    const uint32_t mb_h   = base_local + OFF_MBAR * 4u + (uint32_t)half * 24u;
    const uint32_t blkA = (uint32_t)(OFF_A + half * 4096 + (int)rank * 512) * 4u;
    const uint32_t blkB = (uint32_t)(OFF_B + half * 4096 + (int)rank * 512) * 4u;
    const uint32_t blkC = (uint32_t)(OFF_C + half * 4096 + (int)rank * 512) * 4u;

    // ---- init (full CTA) ----
    for (int i = tid; i < 2048; i += 512) {
        int k4 = i >> 5, c = i & 31;
        int gidx = k4 * 256 + (int)rank * 32 + c;
        w1[i] = g_Pw1[gidx];
        w2[i] = g_Pw2[gidx];
        t1[i] = g_Pt1[gidx];
        t2[i] = g_Pt2[gidx];
    }
    // h state, block-major per half: idx = hf*4096 + blk*512 + row*32 + c.
    // REGION IS 8192 FLOATS TOTAL (R13 bug: looped to 16384 -> hf=2,3 -> OOB).
    for (int i = tid; i < 8192; i += 512) {
        int hf = i >> 12, rem = i & 4095;
        int blk = rem >> 9, rem2 = rem & 511, row = rem2 >> 5, c = rem2 & 31;
        float v;
        if (l_start == 0) {
            v = (blk == 0 && c == 0) ? 1.0f : 0.0f;
        } else {
            v = out[((long)((blockIdx.x >> 3) * 32 + hf * 16 + row) * LL + (l_start - 1)) * SAA
                    + blk * 32 + c];
        }
        sm[OFF_A + i] = v;
    }
    if (tid == 0) {
#pragma unroll
        for (int hf = 0; hf < 2; hf++) {
            uint32_t mb = base_local + OFF_MBAR * 4u + (uint32_t)hf * 24u;
            mbar_init(mb + 0, 1);   // hbar exchange
            mbar_init(mb + 8, 1);   // LRv exchange
            mbar_init(mb + 16, 1);  // h exchange
        }
    }
    __syncthreads();
    cluster_sync();   // all CTAs: buffers + mbarriers ready

    const float h1s = h1[sg];
    float hold[2], zt[2];
#pragma unroll
    for (int t = 0; t < 2; t++) {
        if (l_start == 0) {
            hold[t] = (sg == 0) ? 1.0f : 0.0f;
        } else {
            hold[t] = out[((long)(b0 + 2 * wh + t) * LL + (l_start - 1)) * SAA + sg];
        }
        zt[t] = 0.0f;
    }

    for (int l = l_start; l < l_end; l++) {
        const uint32_t par = (uint32_t)((l - l_start) & 1);

        // Prefetch per-token data for this thread's 2 finalize rows.
        float pg1[2], pg2[2], plt[2];
#pragma unroll
        for (int t = 0; t < 2; t++) {
            long gb = ((long)(b0 + 2 * wh + t) * LL + l) * 256 + sg;
            pg1[t] = g_G1[gb];
            pg2[t] = g_G2[gb];
            plt[t] = g_Lseq[gb];
        }

        // ================= Phase 1: az/ar matmuls (Wss1, Wss2) =================
        {
            ull az[8], ar[8];
#pragma unroll
            for (int t = 0; t < 8; t++) { az[t] = 0ULL; ar[t] = 0ULL; }

#pragma unroll 4
            for (int kk = 0; kk < 16; kk++) {
                int k4 = kb4 + kk;
                int bo = (k4 >> 3) * 512 + (k4 & 7) * 4;    // block-major act offset
                ulonglong2 W1 = *reinterpret_cast<const ulonglong2*>(&w1[k4 * 32 + col]);
                ulonglong2 W2 = *reinterpret_cast<const ulonglong2*>(&w2[k4 * 32 + col]);
#pragma unroll
                for (int t = 0; t < 8; t++) {
                    ulonglong2 hv = *reinterpret_cast<const ulonglong2*>(&Ah[bo + (rbase + t) * 32]);
                    ffma2(az[t], hv.x, W1.x);
                    ffma2(az[t], hv.y, W1.y);
                    ffma2(ar[t], hv.x, W2.x);
                    ffma2(ar[t], hv.y, W2.y);
                }
            }
#pragma unroll
            for (int t = 0; t < 8; t++) {
                int r = rbase + t;
                Ch[r * 128 + col * 4 + ks]        = sum2(az[t]);
                Ch[2048 + r * 128 + col * 4 + ks] = sum2(ar[t]);
            }
        }
        half_bar(barid);
        // ---- P1 finalize: gates + hbar into local block of Bh ----
#pragma unroll
        for (int t = 0; t < 2; t++) {
            int r = 2 * wh + t;
            float4 pz = *reinterpret_cast<const float4*>(&Ch[r * 128 + col * 4]);
            float4 pr = *reinterpret_cast<const float4*>(&Ch[2048 + r * 128 + col * 4]);
            float z  = sigmoid_f(pz.x + pz.y + pz.z + pz.w + pg1[t]);
            float rr = sigmoid_f(pr.x + pr.y + pr.z + pr.w + pg2[t]);
            zt[t] = z;
            Bh[(int)rank * 512 + r * 32 + col] = (1.0f - rr) * h1s + rr * hold[t];
        }
        half_bar(barid);
        if (ht == 0) {
            fence_proxy_async_cta();
            mbar_arrive_expect_tx(mb_h + 0, XTX);
#pragma unroll
            for (int d = 0; d < 8; d++) {
                if (d == (int)rank) continue;
                bulk_copy_peer(mapa_u32(base_local + blkB, d), base_local + blkB,
                               2048u, mapa_u32(mb_h + 0, d));
            }
        }
        mbar_wait_parity(mb_h + 0, par);

        // ====== Phase 2: Rv = hbar @ tr1  AND  aw = hbar @ tw ======
        {
            ull av[8], aw[8];
#pragma unroll
            for (int t = 0; t < 8; t++) { av[t] = 0ULL; aw[t] = 0ULL; }

            // depth-8 register pipeline for the Ptw (L2) loads
            ulonglong2 wvbuf[8];
#pragma unroll
            for (int p = 0; p < 8; p++) {
                wvbuf[p] = *reinterpret_cast<const ulonglong2*>(&g_Ptw[(kb4 + p) * 256 + sg]);
            }

#pragma unroll
            for (int kk = 0; kk < 16; kk++) {
                int k4 = kb4 + kk;
                int bo = (k4 >> 3) * 512 + (k4 & 7) * 4;
                ulonglong2 W  = *reinterpret_cast<const ulonglong2*>(&t1[k4 * 32 + col]);
                ulonglong2 Wv = wvbuf[kk & 7];
                if (kk < 8) {
                    wvbuf[kk & 7] = *reinterpret_cast<const ulonglong2*>(
                        &g_Ptw[(kb4 + kk + 8) * 256 + sg]);
                }
#pragma unroll
                for (int t = 0; t < 8; t++) {
                    ulonglong2 hb = *reinterpret_cast<const ulonglong2*>(&Bh[bo + (rbase + t) * 32]);
                    ffma2(av[t], hb.x, W.x);
                    ffma2(av[t], hb.y, W.y);
                    ffma2(aw[t], hb.x, Wv.x);
                    ffma2(aw[t], hb.y, Wv.y);
                }
            }
            half_bar(barid);   // all hbar reads done before aw partials land in Bh
#pragma unroll
            for (int t = 0; t < 8; t++) {
                int r = rbase + t;
                Ah[r * 128 + col * 4 + ks] = sum2(av[t]);   // Ah dead (h in regs)
                Bh[r * 128 + col * 4 + ks] = sum2(aw[t]);
            }
        }
        half_bar(barid);
        // ---- P2 finalize: LRv = Rv * Lt into local block of Ch ----
#pragma unroll
        for (int t = 0; t < 2; t++) {
            int r = 2 * wh + t;
            float4 pv = *reinterpret_cast<const float4*>(&Ah[r * 128 + col * 4]);
            Ch[(int)rank * 512 + r * 32 + col] = (pv.x + pv.y + pv.z + pv.w) * plt[t];
        }
        half_bar(barid);
        if (ht == 0) {
            fence_proxy_async_cta();
            mbar_arrive_expect_tx(mb_h + 8, XTX);
#pragma unroll
            for (int d = 0; d < 8; d++) {
                if (d == (int)rank) continue;
                bulk_copy_peer(mapa_u32(base_local + blkC, d), base_local + blkC,
                               2048u, mapa_u32(mb_h + 8, d));
            }
        }
        mbar_wait_parity(mb_h + 8, par);

        // ================= Phase 3: ah = LRv @ t2 =================
        {
            ull ah[8];
#pragma unroll
            for (int t = 0; t < 8; t++) ah[t] = 0ULL;

#pragma unroll 4
            for (int kk = 0; kk < 16; kk++) {
                int k4 = kb4 + kk;
                int bo = (k4 >> 3) * 512 + (k4 & 7) * 4;
                ulonglong2 Wu = *reinterpret_cast<const ulonglong2*>(&t2[k4 * 32 + col]);
#pragma unroll
                for (int t = 0; t < 8; t++) {
                    ulonglong2 lr = *reinterpret_cast<const ulonglong2*>(&Ch[bo + (rbase + t) * 32]);
                    ffma2(ah[t], lr.x, Wu.x);
                    ffma2(ah[t], lr.y, Wu.y);
                }
            }
            half_bar(barid);              // all LRv reads done before overwrite
#pragma unroll
            for (int t = 0; t < 8; t++) {
                int r = rbase + t;
                Ch[r * 128 + col * 4 + ks] = sum2(ah[t]);
            }
        }
        half_bar(barid);
        // ---- P3 finalize: hid = relu(ah + aw), blend, h into local block of Ah ----
#pragma unroll
        for (int t = 0; t < 2; t++) {
            int r = 2 * wh + t;
            float4 ph = *reinterpret_cast<const float4*>(&Ch[r * 128 + col * 4]);
            float4 pw = *reinterpret_cast<const float4*>(&Bh[r * 128 + col * 4]);
            float hid = fmaxf(ph.x + ph.y + ph.z + ph.w + pw.x + pw.y + pw.z + pw.w, 0.0f);
            float hn  = (1.0f - zt[t]) * hold[t] + zt[t] * hid;
            hold[t] = hn;
            Ah[(int)rank * 512 + r * 32 + col] = hn;
            out[((long)(b0 + r) * LL + l) * SAA + sg] = hn;
        }
        half_bar(barid);
        if (ht == 0) {
            fence_proxy_async_cta();
            mbar_arrive_expect_tx(mb_h + 16, XTX);
#pragma unroll
            for (int d = 0; d < 8; d++) {
                if (d == (int)rank) continue;
                bulk_copy_peer(mapa_u32(base_local + blkA, d), base_local + blkA,
                               2048u, mapa_u32(mb_h + 16, d));
            }
        }
        mbar_wait_parity(mb_h + 16, par);
    }

    // Drain outbound bulk copies (engine may still be reading our SMEM),
    // then rendezvous so no CTA exits while peers' copies are in flight.
    if (ht == 0) bulk_drain();
    __syncthreads();
    cluster_sync();
}

// ---------------------------------------------------------------------------
// Launch. Scan split in two so ncu (-s 5 -c 1) lands on a scan launch.
// ---------------------------------------------------------------------------
extern "C" void kernel_launch(void* const* d_in, const int* in_sizes, int n_in,
                              void* d_out, int out_size) {
    const int*   ids       = (const int*)  d_in[0];
    const float* embedding = (const float*)d_in[2];
    const float* embed_r   = (const float*)d_in[3];
    const float* erg       = (const float*)d_in[4];
    const float* Wss1      = (const float*)d_in[5];
    const float* Wrs1      = (const float*)d_in[6];
    const float* bs1       = (const float*)d_in[7];
    const float* Wss2      = (const float*)d_in[8];
    const float* Wrs2      = (const float*)d_in[9];
    const float* bs2       = (const float*)d_in[10];
    const float* beta      = (const float*)d_in[11];
    const float* tw        = (const float*)d_in[12];
    const float* tr1       = (const float*)d_in[13];
    const float* tr2       = (const float*)d_in[14];
    const float* h1        = (const float*)d_in[15];
    float* out = (float*)d_out;

    static bool attr_done = false;
    if (!attr_done) {
        cudaFuncSetAttribute(scan_kernel,
                             cudaFuncAttributeMaxDynamicSharedMemorySize,
                             SMEM_FLOATS * sizeof(float));
        attr_done = true;
    }

    pack_weights<<<8 * 75, 256>>>(Wss1, Wss2, Wrs1, Wrs2, tr1, tw, tr2, erg);   // idx 0
    precompute_kernel<<<(BB * LL) / TOK, 256>>>(ids, embedding, embed_r,
                                                bs1, bs2, beta);                 // idx 1
    scan_kernel<<<128, 512, SMEM_FLOATS * sizeof(float)>>>(h1, out, 0, 64);      // idx 2
    scan_kernel<<<128, 512, SMEM_FLOATS * sizeof(float)>>>(h1, out, 64, 128);    // idx 3
}